// round 4
// baseline (speedup 1.0000x reference)
#include <cuda_runtime.h>
#include <math.h>
#include <stdint.h>

// ---------------------------------------------------------------------------
// Problem constants (shapes fixed by the reference)
// ---------------------------------------------------------------------------
#define NN   100000   // nodes
#define EE   800000   // edges
#define NLB  200000   // labeled edges

// ---------------------------------------------------------------------------
// Scratch (static device globals — allocation-free, graph-capture safe)
// ---------------------------------------------------------------------------
__device__ float    g_h0  [(size_t)NN * 256];  // layer0 h = x@W0   [N,H=4,C=64]
__device__ float    g_agg [(size_t)NN * 256];  // agg buffer (reused layer1, needs N*128)
__device__ float    g_out0[(size_t)NN * 64];   // layer0 output (post mean+bias+relu)
__device__ float    g_h1  [(size_t)NN * 128];  // layer1 h               [N,4,32]
__device__ float    g_out1[(size_t)NN * 32];   // layer1 output
__device__ float    g_z   [(size_t)NN * 32];   // z = out1@lin_w + lin_b
__device__ float    g_asrc[(size_t)NN * 4];
__device__ float    g_adst[(size_t)NN * 4];
__device__ unsigned g_menc[(size_t)NN * 4];    // encoded segment-max
__device__ float    g_den [(size_t)NN * 4];    // softmax denominator
__device__ float    g_ebuf[(size_t)EE * 4];    // per-edge e -> exp -> alpha (in place)
__device__ float    g_e1  [(size_t)NN * 32];
__device__ float    g_e2  [(size_t)NN * 64];
__device__ float    g_e3  [(size_t)NN * 96];

static inline int cdiv(long long a, long long b) { return (int)((a + b - 1) / b); }

// ---------------------------------------------------------------------------
// Fills
// ---------------------------------------------------------------------------
__global__ void fill_f32(float* p, float v, long long n) {
    long long i = (long long)blockIdx.x * blockDim.x + threadIdx.x;
    if (i < n) p[i] = v;
}
__global__ void fill_u32(unsigned* p, unsigned v, long long n) {
    long long i = (long long)blockIdx.x * blockDim.x + threadIdx.x;
    if (i < n) p[i] = v;
}

// ---------------------------------------------------------------------------
// Generic tiled SGEMM: C[M,N] = A[M,K] @ B[K,N]  (+bias)(+relu)
// BM=BN=64, BK=16, 256 threads, 4x4 register tile.
// Requires K % 16 == 0 (holds for all call sites: 32/64/96).
// ---------------------------------------------------------------------------
__global__ __launch_bounds__(256)
void sgemm64(const float* __restrict__ A, const float* __restrict__ B,
             const float* __restrict__ bias, float* __restrict__ C,
             int M, int N, int K, int relu)
{
    const int BM = 64, BN = 64, BK = 16;
    __shared__ __align__(16) float As[BK][BM + 4];  // transposed, +4 pad (keeps 16B align)
    __shared__ __align__(16) float Bs[BK][BN];

    int tid = threadIdx.x;
    int tx  = tid & 15;          // 16 col groups
    int ty  = tid >> 4;          // 16 row groups
    int rowBase = blockIdx.y * BM;
    int colBase = blockIdx.x * BN;

    // A load: one float4 per thread per k-chunk
    int ar = tid >> 2;           // 0..63 (tile row)
    int ac = (tid & 3) * 4;      // 0,4,8,12 (k offset)

    float acc[4][4] = {};

    for (int k0 = 0; k0 < K; k0 += BK) {
        float4 av = make_float4(0.f, 0.f, 0.f, 0.f);
        int gr = rowBase + ar;
        if (gr < M) av = *(const float4*)(A + (size_t)gr * K + k0 + ac);
        As[ac + 0][ar] = av.x; As[ac + 1][ar] = av.y;
        As[ac + 2][ar] = av.z; As[ac + 3][ar] = av.w;

        #pragma unroll
        for (int i = 0; i < 4; i++) {
            int idx = tid + i * 256;
            int r = idx >> 6, c = idx & 63;
            int gc = colBase + c;
            Bs[r][c] = (gc < N) ? B[(size_t)(k0 + r) * N + gc] : 0.f;
        }
        __syncthreads();

        #pragma unroll
        for (int k = 0; k < BK; k++) {
            float4 a4 = *(const float4*)&As[k][ty * 4];
            float4 b4 = *(const float4*)&Bs[k][tx * 4];
            float am[4] = {a4.x, a4.y, a4.z, a4.w};
            float bm[4] = {b4.x, b4.y, b4.z, b4.w};
            #pragma unroll
            for (int m = 0; m < 4; m++)
                #pragma unroll
                for (int n = 0; n < 4; n++)
                    acc[m][n] += am[m] * bm[n];
        }
        __syncthreads();
    }

    #pragma unroll
    for (int m = 0; m < 4; m++) {
        int gr = rowBase + ty * 4 + m;
        if (gr >= M) continue;
        #pragma unroll
        for (int n = 0; n < 4; n++) {
            int gc = colBase + tx * 4 + n;
            if (gc >= N) continue;
            float v = acc[m][n];
            if (bias) v += bias[gc];
            if (relu) v = fmaxf(v, 0.f);
            C[(size_t)gr * N + gc] = v;
        }
    }
}

// ---------------------------------------------------------------------------
// Per-node attention logits: asrc[n,h] = dot(h[n,h,:], a_src[h,:]), same for dst.
// One warp per node.
// ---------------------------------------------------------------------------
template <int C>
__global__ void alpha_kernel(const float* __restrict__ h,
                             const float* __restrict__ a_s,
                             const float* __restrict__ a_d,
                             float* __restrict__ asrc, float* __restrict__ adst, int N)
{
    int gw   = (int)((blockIdx.x * (long long)blockDim.x + threadIdx.x) >> 5);
    int lane = threadIdx.x & 31;
    if (gw >= N) return;
    const float* hr = h + (size_t)gw * 4 * C;
    #pragma unroll
    for (int hh = 0; hh < 4; hh++) {
        float s1 = 0.f, s2 = 0.f;
        #pragma unroll
        for (int c = lane; c < C; c += 32) {
            float hv = hr[hh * C + c];
            s1 += hv * a_s[hh * C + c];
            s2 += hv * a_d[hh * C + c];
        }
        #pragma unroll
        for (int o = 16; o; o >>= 1) {
            s1 += __shfl_down_sync(0xffffffffu, s1, o);
            s2 += __shfl_down_sync(0xffffffffu, s2, o);
        }
        if (lane == 0) {
            asrc[(size_t)gw * 4 + hh] = s1;
            adst[(size_t)gw * 4 + hh] = s2;
        }
    }
}

// ---------------------------------------------------------------------------
// Edge passes. Thread per (edge, head).
// ---------------------------------------------------------------------------
__global__ void edge_max_kernel(const int* __restrict__ ei,
                                const float* __restrict__ asrc, const float* __restrict__ adst,
                                float* __restrict__ ebuf, unsigned* __restrict__ menc, int E)
{
    int gid = blockIdx.x * blockDim.x + threadIdx.x;
    if (gid >= E * 4) return;
    int e = gid >> 2, hh = gid & 3;
    int s = ei[e], d = ei[E + e];
    float v = asrc[(size_t)s * 4 + hh] + adst[(size_t)d * 4 + hh];
    v = (v > 0.f) ? v : 0.2f * v;                      // leaky_relu(0.2)
    ebuf[gid] = v;
    unsigned b = __float_as_uint(v);
    unsigned k = (b & 0x80000000u) ? ~b : (b | 0x80000000u);   // monotonic float->uint
    atomicMax(menc + (size_t)d * 4 + hh, k);
}

__global__ void edge_sum_kernel(const int* __restrict__ ei,
                                float* __restrict__ ebuf,
                                const unsigned* __restrict__ menc,
                                float* __restrict__ den, int E)
{
    int gid = blockIdx.x * blockDim.x + threadIdx.x;
    if (gid >= E * 4) return;
    int e = gid >> 2, hh = gid & 3;
    int d = ei[E + e];
    unsigned k = menc[(size_t)d * 4 + hh];
    float m = (k & 0x80000000u) ? __uint_as_float(k & 0x7fffffffu) : __uint_as_float(~k);
    float ex = expf(ebuf[gid] - m);
    ebuf[gid] = ex;
    atomicAdd(den + (size_t)d * 4 + hh, ex);
}

__global__ void edge_alpha_kernel(const int* __restrict__ ei,
                                  float* __restrict__ ebuf,
                                  const float* __restrict__ den, int E)
{
    int gid = blockIdx.x * blockDim.x + threadIdx.x;
    if (gid >= E * 4) return;
    int e = gid >> 2, hh = gid & 3;
    int d = ei[E + e];
    ebuf[gid] = ebuf[gid] / (den[(size_t)d * 4 + hh] + 1e-16f);
}

// agg[dst,h,:] += h[src,h,:] * alpha   — C threads per edge, float4 each,
// vector RED (red.global.add.v4.f32) to cut LSU issue cost 4x vs scalar atomics.
template <int C>
__global__ void edge_agg_kernel(const int* __restrict__ ei,
                                const float* __restrict__ h,
                                const float* __restrict__ alpha,
                                float* __restrict__ agg, int E)
{
    int gid = blockIdx.x * blockDim.x + threadIdx.x;   // up to E*C = 51.2M, fits int
    int e = gid / C;
    int t = gid % C;
    if (e >= E) return;
    int s  = ei[e], d = ei[E + e];
    int hh = t / (C / 4);
    float al = alpha[(size_t)e * 4 + hh];
    float4 hv = *(const float4*)(h + (size_t)s * 4 * C + t * 4);
    float* p = agg + (size_t)d * 4 * C + t * 4;
    asm volatile("red.global.add.v4.f32 [%0], {%1,%2,%3,%4};"
                 :: "l"(p), "f"(hv.x * al), "f"(hv.y * al), "f"(hv.z * al), "f"(hv.w * al)
                 : "memory");
}

// out[n,c] = relu( mean_h(agg[n,h,c]) + bias[c] )
template <int C>
__global__ void finalize_kernel(const float* __restrict__ agg, const float* __restrict__ bias,
                                float* __restrict__ out, int N)
{
    int gid = blockIdx.x * blockDim.x + threadIdx.x;
    if (gid >= N * C) return;
    int n = gid / C, c = gid % C;
    const float* ar = agg + (size_t)n * 4 * C;
    float s = ar[c] + ar[C + c] + ar[2 * C + c] + ar[3 * C + c];
    out[gid] = fmaxf(0.25f * s + bias[c], 0.f);
}

// link[i] = dot(z[a], z[b]) over 32 channels
__global__ void link_kernel(const int* __restrict__ eli, const float* __restrict__ z,
                            float* __restrict__ out, int NL)
{
    int i = blockIdx.x * blockDim.x + threadIdx.x;
    if (i >= NL) return;
    int a = eli[i], b = eli[NL + i];
    const float4* za = (const float4*)(z + (size_t)a * 32);
    const float4* zb = (const float4*)(z + (size_t)b * 32);
    float s = 0.f;
    #pragma unroll
    for (int j = 0; j < 8; j++) {
        float4 u = za[j], v = zb[j];
        s += u.x * v.x + u.y * v.y + u.z * v.z + u.w * v.w;
    }
    out[i] = s;
}

// ---------------------------------------------------------------------------
// Launch
// ---------------------------------------------------------------------------
extern "C" void kernel_launch(void* const* d_in, const int* in_sizes, int n_in,
                              void* d_out, int out_size)
{
    const float* x   = (const float*)d_in[0];
    const int*   ei  = (const int*)  d_in[1];
    const int*   eli = (const int*)  d_in[2];
    const float* W0  = (const float*)d_in[3];
    const float* as0 = (const float*)d_in[4];
    const float* ad0 = (const float*)d_in[5];
    const float* b0  = (const float*)d_in[6];
    const float* W1  = (const float*)d_in[7];
    const float* as1 = (const float*)d_in[8];
    const float* ad1 = (const float*)d_in[9];
    const float* b1  = (const float*)d_in[10];
    const float* lw  = (const float*)d_in[11];
    const float* lb  = (const float*)d_in[12];
    const float* d1w = (const float*)d_in[13];
    const float* d1b = (const float*)d_in[14];
    const float* d2w = (const float*)d_in[15];
    const float* d2b = (const float*)d_in[16];
    const float* d3w = (const float*)d_in[17];
    const float* d3b = (const float*)d_in[18];
    const float* d4w = (const float*)d_in[19];
    const float* d4b = (const float*)d_in[20];

    int N  = in_sizes[0] / 64;
    int E  = in_sizes[1] / 2;
    int NL = in_sizes[2] / 2;
    float* out = (float*)d_out;

    float *h0, *agg, *out0, *h1, *out1, *z, *asrc, *adst, *den, *ebuf, *e1, *e2, *e3;
    unsigned* menc;
    cudaGetSymbolAddress((void**)&h0,   g_h0);
    cudaGetSymbolAddress((void**)&agg,  g_agg);
    cudaGetSymbolAddress((void**)&out0, g_out0);
    cudaGetSymbolAddress((void**)&h1,   g_h1);
    cudaGetSymbolAddress((void**)&out1, g_out1);
    cudaGetSymbolAddress((void**)&z,    g_z);
    cudaGetSymbolAddress((void**)&asrc, g_asrc);
    cudaGetSymbolAddress((void**)&adst, g_adst);
    cudaGetSymbolAddress((void**)&menc, g_menc);
    cudaGetSymbolAddress((void**)&den,  g_den);
    cudaGetSymbolAddress((void**)&ebuf, g_ebuf);
    cudaGetSymbolAddress((void**)&e1,   g_e1);
    cudaGetSymbolAddress((void**)&e2,   g_e2);
    cudaGetSymbolAddress((void**)&e3,   g_e3);

    dim3 blk(256);
    int gNH   = cdiv((long long)N * 4, 256);
    int gE4   = cdiv((long long)E * 4, 256);
    int gRowT = cdiv(N, 64);

    // ------------------ GAT layer 0 (in 64 -> 4 heads x 64) ------------------
    sgemm64<<<dim3(4, gRowT), blk>>>(x, W0, nullptr, h0, N, 256, 64, 0);
    alpha_kernel<64><<<cdiv(N, 8), blk>>>(h0, as0, ad0, asrc, adst, N);
    fill_u32<<<gNH, blk>>>(menc, 0u, (long long)N * 4);
    fill_f32<<<gNH, blk>>>(den, 0.f, (long long)N * 4);
    fill_f32<<<cdiv((long long)N * 256, 256), blk>>>(agg, 0.f, (long long)N * 256);
    edge_max_kernel  <<<gE4, blk>>>(ei, asrc, adst, ebuf, menc, E);
    edge_sum_kernel  <<<gE4, blk>>>(ei, ebuf, menc, den, E);
    edge_alpha_kernel<<<gE4, blk>>>(ei, ebuf, den, E);
    edge_agg_kernel<64><<<cdiv((long long)E * 64, 256), blk>>>(ei, h0, ebuf, agg, E);
    finalize_kernel<64><<<cdiv((long long)N * 64, 256), blk>>>(agg, b0, out0, N);

    // ------------------ GAT layer 1 (in 64 -> 4 heads x 32) ------------------
    sgemm64<<<dim3(2, gRowT), blk>>>(out0, W1, nullptr, h1, N, 128, 64, 0);
    alpha_kernel<32><<<cdiv(N, 8), blk>>>(h1, as1, ad1, asrc, adst, N);
    fill_u32<<<gNH, blk>>>(menc, 0u, (long long)N * 4);
    fill_f32<<<gNH, blk>>>(den, 0.f, (long long)N * 4);
    fill_f32<<<cdiv((long long)N * 128, 256), blk>>>(agg, 0.f, (long long)N * 128);
    edge_max_kernel  <<<gE4, blk>>>(ei, asrc, adst, ebuf, menc, E);
    edge_sum_kernel  <<<gE4, blk>>>(ei, ebuf, menc, den, E);
    edge_alpha_kernel<<<gE4, blk>>>(ei, ebuf, den, E);
    edge_agg_kernel<32><<<cdiv((long long)E * 32, 256), blk>>>(ei, h1, ebuf, agg, E);
    finalize_kernel<32><<<cdiv((long long)N * 32, 256), blk>>>(agg, b1, out1, N);

    // ------------------ z = out1 @ lin_w + lin_b ------------------
    sgemm64<<<dim3(1, gRowT), blk>>>(out1, lw, lb, z, N, 32, 32, 0);

    // ------------------ link decode -> d_out[0 : NL] ------------------
    link_kernel<<<cdiv(NL, 256), blk>>>(eli, z, out, NL);

    // ------------------ expression MLP -> d_out[NL : NL + N*500] ------------------
    sgemm64<<<dim3(1, gRowT), blk>>>(z,  d1w, d1b, e1, N, 32,  32, 1);
    sgemm64<<<dim3(1, gRowT), blk>>>(e1, d2w, d2b, e2, N, 64,  32, 1);
    sgemm64<<<dim3(2, gRowT), blk>>>(e2, d3w, d3b, e3, N, 96,  64, 1);
    sgemm64<<<dim3(8, gRowT), blk>>>(e3, d4w, d4b, out + NL, N, 500, 96, 0);
}

// round 5
// speedup vs baseline: 1.0034x; 1.0034x over previous
#include <cuda_runtime.h>
#include <math.h>
#include <stdint.h>

// ---------------------------------------------------------------------------
// Problem constants (shapes fixed by the reference)
// ---------------------------------------------------------------------------
#define NN   100000   // nodes
#define EE   800000   // edges
#define NLB  200000   // labeled edges

// ---------------------------------------------------------------------------
// Scratch (static device globals — allocation-free, graph-capture safe)
// ---------------------------------------------------------------------------
__device__ float    g_h0  [(size_t)NN * 256];  // layer0 h = x@W0   [N,H=4,C=64]
__device__ float    g_agg [(size_t)NN * 256];  // agg buffer (reused layer1, needs N*128)
__device__ float    g_out0[(size_t)NN * 64];   // layer0 output (post mean+bias+relu)
__device__ float    g_h1  [(size_t)NN * 128];  // layer1 h               [N,4,32]
__device__ float    g_out1[(size_t)NN * 32];   // layer1 output
__device__ float    g_z   [(size_t)NN * 32];   // z = out1@lin_w + lin_b
__device__ float    g_asrc[(size_t)NN * 4];
__device__ float    g_adst[(size_t)NN * 4];
__device__ unsigned g_menc[(size_t)NN * 4];    // encoded segment-max
__device__ float    g_den [(size_t)NN * 4];    // softmax denominator
__device__ float    g_ebuf[(size_t)EE * 4];    // per-edge e -> exp -> alpha (in place)
__device__ float    g_e1  [(size_t)NN * 32];
__device__ float    g_e2  [(size_t)NN * 64];
__device__ float    g_e3  [(size_t)NN * 96];

static inline int cdiv(long long a, long long b) { return (int)((a + b - 1) / b); }

// ---------------------------------------------------------------------------
// Fills
// ---------------------------------------------------------------------------
__global__ void fill_f32(float* p, float v, long long n) {
    long long i = (long long)blockIdx.x * blockDim.x + threadIdx.x;
    if (i < n) p[i] = v;
}
__global__ void fill_u32(unsigned* p, unsigned v, long long n) {
    long long i = (long long)blockIdx.x * blockDim.x + threadIdx.x;
    if (i < n) p[i] = v;
}

// ---------------------------------------------------------------------------
// Generic tiled SGEMM: C[M,N] = A[M,K] @ B[K,N]  (+bias)(+relu)
// BM=BN=64, BK=16, 256 threads, 4x4 register tile.
// Requires K % 16 == 0 (holds for all call sites: 32/64/96).
// ---------------------------------------------------------------------------
__global__ __launch_bounds__(256)
void sgemm64(const float* __restrict__ A, const float* __restrict__ B,
             const float* __restrict__ bias, float* __restrict__ C,
             int M, int N, int K, int relu)
{
    const int BM = 64, BN = 64, BK = 16;
    __shared__ __align__(16) float As[BK][BM + 4];  // transposed, +4 pad (keeps 16B align)
    __shared__ __align__(16) float Bs[BK][BN];

    int tid = threadIdx.x;
    int tx  = tid & 15;          // 16 col groups
    int ty  = tid >> 4;          // 16 row groups
    int rowBase = blockIdx.y * BM;
    int colBase = blockIdx.x * BN;

    // A load: one float4 per thread per k-chunk
    int ar = tid >> 2;           // 0..63 (tile row)
    int ac = (tid & 3) * 4;      // 0,4,8,12 (k offset)

    float acc[4][4] = {};

    for (int k0 = 0; k0 < K; k0 += BK) {
        float4 av = make_float4(0.f, 0.f, 0.f, 0.f);
        int gr = rowBase + ar;
        if (gr < M) av = *(const float4*)(A + (size_t)gr * K + k0 + ac);
        As[ac + 0][ar] = av.x; As[ac + 1][ar] = av.y;
        As[ac + 2][ar] = av.z; As[ac + 3][ar] = av.w;

        #pragma unroll
        for (int i = 0; i < 4; i++) {
            int idx = tid + i * 256;
            int r = idx >> 6, c = idx & 63;
            int gc = colBase + c;
            Bs[r][c] = (gc < N) ? B[(size_t)(k0 + r) * N + gc] : 0.f;
        }
        __syncthreads();

        #pragma unroll
        for (int k = 0; k < BK; k++) {
            float4 a4 = *(const float4*)&As[k][ty * 4];
            float4 b4 = *(const float4*)&Bs[k][tx * 4];
            float am[4] = {a4.x, a4.y, a4.z, a4.w};
            float bm[4] = {b4.x, b4.y, b4.z, b4.w};
            #pragma unroll
            for (int m = 0; m < 4; m++)
                #pragma unroll
                for (int n = 0; n < 4; n++)
                    acc[m][n] += am[m] * bm[n];
        }
        __syncthreads();
    }

    #pragma unroll
    for (int m = 0; m < 4; m++) {
        int gr = rowBase + ty * 4 + m;
        if (gr >= M) continue;
        #pragma unroll
        for (int n = 0; n < 4; n++) {
            int gc = colBase + tx * 4 + n;
            if (gc >= N) continue;
            float v = acc[m][n];
            if (bias) v += bias[gc];
            if (relu) v = fmaxf(v, 0.f);
            C[(size_t)gr * N + gc] = v;
        }
    }
}

// ---------------------------------------------------------------------------
// Per-node attention logits: asrc[n,h] = dot(h[n,h,:], a_src[h,:]), same for dst.
// One warp per node.
// ---------------------------------------------------------------------------
template <int C>
__global__ void alpha_kernel(const float* __restrict__ h,
                             const float* __restrict__ a_s,
                             const float* __restrict__ a_d,
                             float* __restrict__ asrc, float* __restrict__ adst, int N)
{
    int gw   = (int)((blockIdx.x * (long long)blockDim.x + threadIdx.x) >> 5);
    int lane = threadIdx.x & 31;
    if (gw >= N) return;
    const float* hr = h + (size_t)gw * 4 * C;
    #pragma unroll
    for (int hh = 0; hh < 4; hh++) {
        float s1 = 0.f, s2 = 0.f;
        #pragma unroll
        for (int c = lane; c < C; c += 32) {
            float hv = hr[hh * C + c];
            s1 += hv * a_s[hh * C + c];
            s2 += hv * a_d[hh * C + c];
        }
        #pragma unroll
        for (int o = 16; o; o >>= 1) {
            s1 += __shfl_down_sync(0xffffffffu, s1, o);
            s2 += __shfl_down_sync(0xffffffffu, s2, o);
        }
        if (lane == 0) {
            asrc[(size_t)gw * 4 + hh] = s1;
            adst[(size_t)gw * 4 + hh] = s2;
        }
    }
}

// ---------------------------------------------------------------------------
// Edge passes. Thread per (edge, head).
// ---------------------------------------------------------------------------
__global__ void edge_max_kernel(const int* __restrict__ ei,
                                const float* __restrict__ asrc, const float* __restrict__ adst,
                                float* __restrict__ ebuf, unsigned* __restrict__ menc, int E)
{
    int gid = blockIdx.x * blockDim.x + threadIdx.x;
    if (gid >= E * 4) return;
    int e = gid >> 2, hh = gid & 3;
    int s = ei[e], d = ei[E + e];
    float v = asrc[(size_t)s * 4 + hh] + adst[(size_t)d * 4 + hh];
    v = (v > 0.f) ? v : 0.2f * v;                      // leaky_relu(0.2)
    ebuf[gid] = v;
    unsigned b = __float_as_uint(v);
    unsigned k = (b & 0x80000000u) ? ~b : (b | 0x80000000u);   // monotonic float->uint
    atomicMax(menc + (size_t)d * 4 + hh, k);
}

__global__ void edge_sum_kernel(const int* __restrict__ ei,
                                float* __restrict__ ebuf,
                                const unsigned* __restrict__ menc,
                                float* __restrict__ den, int E)
{
    int gid = blockIdx.x * blockDim.x + threadIdx.x;
    if (gid >= E * 4) return;
    int e = gid >> 2, hh = gid & 3;
    int d = ei[E + e];
    unsigned k = menc[(size_t)d * 4 + hh];
    float m = (k & 0x80000000u) ? __uint_as_float(k & 0x7fffffffu) : __uint_as_float(~k);
    float ex = expf(ebuf[gid] - m);
    ebuf[gid] = ex;
    atomicAdd(den + (size_t)d * 4 + hh, ex);
}

__global__ void edge_alpha_kernel(const int* __restrict__ ei,
                                  float* __restrict__ ebuf,
                                  const float* __restrict__ den, int E)
{
    int gid = blockIdx.x * blockDim.x + threadIdx.x;
    if (gid >= E * 4) return;
    int e = gid >> 2, hh = gid & 3;
    int d = ei[E + e];
    ebuf[gid] = ebuf[gid] / (den[(size_t)d * 4 + hh] + 1e-16f);
}

// agg[dst,h,:] += h[src,h,:] * alpha   — C threads per edge, float4 each,
// vector RED (red.global.add.v4.f32) to cut LSU issue cost 4x vs scalar atomics.
template <int C>
__global__ void edge_agg_kernel(const int* __restrict__ ei,
                                const float* __restrict__ h,
                                const float* __restrict__ alpha,
                                float* __restrict__ agg, int E)
{
    int gid = blockIdx.x * blockDim.x + threadIdx.x;   // up to E*C = 51.2M, fits int
    int e = gid / C;
    int t = gid % C;
    if (e >= E) return;
    int s  = ei[e], d = ei[E + e];
    int hh = t / (C / 4);
    float al = alpha[(size_t)e * 4 + hh];
    float4 hv = *(const float4*)(h + (size_t)s * 4 * C + t * 4);
    float* p = agg + (size_t)d * 4 * C + t * 4;
    asm volatile("red.global.add.v4.f32 [%0], {%1,%2,%3,%4};"
                 :: "l"(p), "f"(hv.x * al), "f"(hv.y * al), "f"(hv.z * al), "f"(hv.w * al)
                 : "memory");
}

// out[n,c] = relu( mean_h(agg[n,h,c]) + bias[c] )
template <int C>
__global__ void finalize_kernel(const float* __restrict__ agg, const float* __restrict__ bias,
                                float* __restrict__ out, int N)
{
    int gid = blockIdx.x * blockDim.x + threadIdx.x;
    if (gid >= N * C) return;
    int n = gid / C, c = gid % C;
    const float* ar = agg + (size_t)n * 4 * C;
    float s = ar[c] + ar[C + c] + ar[2 * C + c] + ar[3 * C + c];
    out[gid] = fmaxf(0.25f * s + bias[c], 0.f);
}

// link[i] = dot(z[a], z[b]) over 32 channels
__global__ void link_kernel(const int* __restrict__ eli, const float* __restrict__ z,
                            float* __restrict__ out, int NL)
{
    int i = blockIdx.x * blockDim.x + threadIdx.x;
    if (i >= NL) return;
    int a = eli[i], b = eli[NL + i];
    const float4* za = (const float4*)(z + (size_t)a * 32);
    const float4* zb = (const float4*)(z + (size_t)b * 32);
    float s = 0.f;
    #pragma unroll
    for (int j = 0; j < 8; j++) {
        float4 u = za[j], v = zb[j];
        s += u.x * v.x + u.y * v.y + u.z * v.z + u.w * v.w;
    }
    out[i] = s;
}

// ---------------------------------------------------------------------------
// Launch
// ---------------------------------------------------------------------------
extern "C" void kernel_launch(void* const* d_in, const int* in_sizes, int n_in,
                              void* d_out, int out_size)
{
    const float* x   = (const float*)d_in[0];
    const int*   ei  = (const int*)  d_in[1];
    const int*   eli = (const int*)  d_in[2];
    const float* W0  = (const float*)d_in[3];
    const float* as0 = (const float*)d_in[4];
    const float* ad0 = (const float*)d_in[5];
    const float* b0  = (const float*)d_in[6];
    const float* W1  = (const float*)d_in[7];
    const float* as1 = (const float*)d_in[8];
    const float* ad1 = (const float*)d_in[9];
    const float* b1  = (const float*)d_in[10];
    const float* lw  = (const float*)d_in[11];
    const float* lb  = (const float*)d_in[12];
    const float* d1w = (const float*)d_in[13];
    const float* d1b = (const float*)d_in[14];
    const float* d2w = (const float*)d_in[15];
    const float* d2b = (const float*)d_in[16];
    const float* d3w = (const float*)d_in[17];
    const float* d3b = (const float*)d_in[18];
    const float* d4w = (const float*)d_in[19];
    const float* d4b = (const float*)d_in[20];

    int N  = in_sizes[0] / 64;
    int E  = in_sizes[1] / 2;
    int NL = in_sizes[2] / 2;
    float* out = (float*)d_out;

    float *h0, *agg, *out0, *h1, *out1, *z, *asrc, *adst, *den, *ebuf, *e1, *e2, *e3;
    unsigned* menc;
    cudaGetSymbolAddress((void**)&h0,   g_h0);
    cudaGetSymbolAddress((void**)&agg,  g_agg);
    cudaGetSymbolAddress((void**)&out0, g_out0);
    cudaGetSymbolAddress((void**)&h1,   g_h1);
    cudaGetSymbolAddress((void**)&out1, g_out1);
    cudaGetSymbolAddress((void**)&z,    g_z);
    cudaGetSymbolAddress((void**)&asrc, g_asrc);
    cudaGetSymbolAddress((void**)&adst, g_adst);
    cudaGetSymbolAddress((void**)&menc, g_menc);
    cudaGetSymbolAddress((void**)&den,  g_den);
    cudaGetSymbolAddress((void**)&ebuf, g_ebuf);
    cudaGetSymbolAddress((void**)&e1,   g_e1);
    cudaGetSymbolAddress((void**)&e2,   g_e2);
    cudaGetSymbolAddress((void**)&e3,   g_e3);

    dim3 blk(256);
    int gNH   = cdiv((long long)N * 4, 256);
    int gE4   = cdiv((long long)E * 4, 256);
    int gRowT = cdiv(N, 64);

    // ------------------ GAT layer 0 (in 64 -> 4 heads x 64) ------------------
    sgemm64<<<dim3(4, gRowT), blk>>>(x, W0, nullptr, h0, N, 256, 64, 0);
    alpha_kernel<64><<<cdiv(N, 8), blk>>>(h0, as0, ad0, asrc, adst, N);
    fill_u32<<<gNH, blk>>>(menc, 0u, (long long)N * 4);
    fill_f32<<<gNH, blk>>>(den, 0.f, (long long)N * 4);
    fill_f32<<<cdiv((long long)N * 256, 256), blk>>>(agg, 0.f, (long long)N * 256);
    edge_max_kernel  <<<gE4, blk>>>(ei, asrc, adst, ebuf, menc, E);
    edge_sum_kernel  <<<gE4, blk>>>(ei, ebuf, menc, den, E);
    edge_alpha_kernel<<<gE4, blk>>>(ei, ebuf, den, E);
    edge_agg_kernel<64><<<cdiv((long long)E * 64, 256), blk>>>(ei, h0, ebuf, agg, E);
    finalize_kernel<64><<<cdiv((long long)N * 64, 256), blk>>>(agg, b0, out0, N);

    // ------------------ GAT layer 1 (in 64 -> 4 heads x 32) ------------------
    sgemm64<<<dim3(2, gRowT), blk>>>(out0, W1, nullptr, h1, N, 128, 64, 0);
    alpha_kernel<32><<<cdiv(N, 8), blk>>>(h1, as1, ad1, asrc, adst, N);
    fill_u32<<<gNH, blk>>>(menc, 0u, (long long)N * 4);
    fill_f32<<<gNH, blk>>>(den, 0.f, (long long)N * 4);
    fill_f32<<<cdiv((long long)N * 128, 256), blk>>>(agg, 0.f, (long long)N * 128);
    edge_max_kernel  <<<gE4, blk>>>(ei, asrc, adst, ebuf, menc, E);
    edge_sum_kernel  <<<gE4, blk>>>(ei, ebuf, menc, den, E);
    edge_alpha_kernel<<<gE4, blk>>>(ei, ebuf, den, E);
    edge_agg_kernel<32><<<cdiv((long long)E * 32, 256), blk>>>(ei, h1, ebuf, agg, E);
    finalize_kernel<32><<<cdiv((long long)N * 32, 256), blk>>>(agg, b1, out1, N);

    // ------------------ z = out1 @ lin_w + lin_b ------------------
    sgemm64<<<dim3(1, gRowT), blk>>>(out1, lw, lb, z, N, 32, 32, 0);

    // ------------------ link decode -> d_out[0 : NL] ------------------
    link_kernel<<<cdiv(NL, 256), blk>>>(eli, z, out, NL);

    // ------------------ expression MLP -> d_out[NL : NL + N*500] ------------------
    sgemm64<<<dim3(1, gRowT), blk>>>(z,  d1w, d1b, e1, N, 32,  32, 1);
    sgemm64<<<dim3(1, gRowT), blk>>>(e1, d2w, d2b, e2, N, 64,  32, 1);
    sgemm64<<<dim3(2, gRowT), blk>>>(e2, d3w, d3b, e3, N, 96,  64, 1);
    sgemm64<<<dim3(8, gRowT), blk>>>(e3, d4w, d4b, out + NL, N, 500, 96, 0);
}